// round 17
// baseline (speedup 1.0000x reference)
#include <cuda_runtime.h>
#include <cuda_bf16.h>
#include <cstdint>

// Problem constants (from reference)
#define H_IMG 240
#define W_IMG 135
#define NPIX  (H_IMG * W_IMG)   // 32400
#define NV    600
#define NF    1000
#define SIGMA_F 1e-4f
#define BLUR_F  9.210240366975850e-4f   // log(1/1e-4 - 1) * 1e-4
#define MARGIN_F 0.032f                 // > sqrt(BLUR_F) = 0.030348
#define F_LEN_F 1000.0f
#define C_PP_F  512.0f
#define CAM_F   1024.0f

// Conservative near-band threshold on NORMALIZED line distance.
#define SQRT_BLUR_SAFE 0.0306f
// SAT cull margin: sqrt(BLUR) + fp slack (cull only when provably unaffected)
#define SAT_MARGIN 0.032f

#define TILE_W 16
#define TILE_H 16          // 2 pixels per thread (rows ty and ty+8)
#define TILES_X 9          // ceil(135/16)
#define TILES_Y 15         // 240/16
#define NTILES  (TILES_X * TILES_Y)   // 135
#define NGROUP  8                      // 1080 CTAs -> single wave
#define FACES_PER_G (NF / NGROUP)      // 125
#define TPB 128
#define PIX_PER_CTA 256

#define DONE_THRESH (-100.0f)
#define SENTINEL    (-1e30f)
#define EXIT_CHECK_MASK 3   // ballot every 4 iterations

// Cross-CTA communication (device globals; zero-init at load, reset by kernel)
__device__ float g_acc[NTILES * NGROUP * PIX_PER_CTA];
__device__ float g_tilepart[NTILES];
__device__ int   g_tile_ticket[NTILES];
__device__ int   g_global_ticket;

// grid: (TILES_X, TILES_Y, NGROUP), block: (16,8)
__global__ void __launch_bounds__(TPB, 8)
fused_sil_kernel(const float* __restrict__ verts,
                 const float* __restrict__ gt,
                 const int*   __restrict__ faces,
                 float* __restrict__ out) {
    // fast-path data, 3 float4/face: (s*nkx, s*nky, s*ck, inv_k) per edge k
    //   L'_k = s*(n.p + c): inside <=> min_k L'_k >= 0 ; |L'| = line distance
    // slow-path data, 3 float4/face: (akx, aky, ab_kx, ab_ky)
    __shared__ float4 s_fast[FACES_PER_G * 3];
    __shared__ float4 s_slow[FACES_PER_G * 3];
    __shared__ float  s_red[TPB];
    __shared__ int    s_wcnt[4];
    __shared__ int    s_n;
    __shared__ int    s_flag;

    int tid  = threadIdx.y * 16 + threadIdx.x;
    int wid  = tid >> 5;
    int lane = tid & 31;

    int gx   = blockIdx.x * TILE_W;
    int gy   = blockIdx.y * TILE_H;
    int grp  = blockIdx.z;
    int tile = blockIdx.y * TILES_X + blockIdx.x;

    // tile pixel-center bounds and center (16x16 pixel tile)
    float tx0 = (float)gx + 0.5f;
    float tx1 = (float)gx + 15.5f;
    float ty0 = (float)gy + 0.5f;
    float ty1 = (float)gy + 15.5f;
    float cxc = 0.5f * (tx0 + tx1);
    float cyc = 0.5f * (ty0 + ty1);
    const float HW = 7.5f;
    const float HH = 7.5f;

    // ---- per-CTA face precompute (registers) + cull (bbox AND edge-SAT) ----
    bool pass = false;
    float4 eF0, eF1, eF2, eS0, eS1, eS2;
    if (tid < FACES_PER_G) {
        int f = grp * FACES_PER_G + tid;
        float pxv[3], pyv[3];
        float tz = 0.0f;
#pragma unroll
        for (int k = 0; k < 3; k++) {
            int vi = faces[f * 3 + k];
            float x = verts[vi * 3 + 0];
            float y = verts[vi * 3 + 1];
            float z = verts[vi * 3 + 2];
            float vx = -x, vy = -y, vz = z;      // R = diag(-1,-1,1)
            tz += vz;
            float zc = fmaxf(vz, 1e-6f);
            pxv[k] = (F_LEN_F * vx / zc + C_PP_F) / CAM_F * (float)W_IMG;
            pyv[k] = (F_LEN_F * vy / zc + C_PP_F) / CAM_F * (float)H_IMG;
        }
        tz *= (1.0f / 3.0f);

        // winding sign: sign of 2*signed area
        float e0x = pxv[1] - pxv[0], e0y = pyv[1] - pyv[0];
        float e1x = pxv[2] - pxv[1], e1y = pyv[2] - pyv[1];
        float area2 = e0x * e1y - e0y * e1x;
        float s = (area2 >= 0.0f) ? 1.0f : -1.0f;

        float4 fast[3], slow[3];
        bool sat = true;
#pragma unroll
        for (int k = 0; k < 3; k++) {
            int k2 = (k + 1) % 3;
            float ax = pxv[k],  ay = pyv[k];
            float abx = pxv[k2] - ax, aby = pyv[k2] - ay;
            float dd  = abx * abx + aby * aby + 1e-12f;
            float inv = 1.0f / dd;
            float rlen = rsqrtf(dd);
            float nx = s * (-aby * rlen);        // premultiplied by winding s
            float ny = s * ( abx * rlen);
            float c  = -(nx * ax + ny * ay);
            fast[k] = make_float4(nx, ny, c, inv);
            slow[k] = make_float4(ax, ay, abx, aby);

            // SAT on edge k: affected pixels have L'_k >= -sqrt(BLUR).
            float Lc = fmaf(nx, cxc, fmaf(ny, cyc, c));
            float maxL = Lc + fabsf(nx) * HW + fabsf(ny) * HH;
            sat = sat && (maxL >= -SAT_MARGIN);
        }
        eF0 = fast[0]; eF1 = fast[1]; eF2 = fast[2];
        eS0 = slow[0]; eS1 = slow[1]; eS2 = slow[2];

        if (tz > 1e-6f) {
            float xmn = fminf(pxv[0], fminf(pxv[1], pxv[2])) - MARGIN_F;
            float xmx = fmaxf(pxv[0], fmaxf(pxv[1], pxv[2])) + MARGIN_F;
            float ymn = fminf(pyv[0], fminf(pyv[1], pyv[2])) - MARGIN_F;
            float ymx = fmaxf(pyv[0], fmaxf(pyv[1], pyv[2])) + MARGIN_F;
            pass = (xmn <= tx1) && (xmx >= tx0) && (ymn <= ty1) && (ymx >= ty0)
                   && sat;
        }
    }

    // ---- deterministic ordered compaction of face DATA into smem ----
    unsigned mask = __ballot_sync(0xffffffffu, pass);
    if (lane == 0) s_wcnt[wid] = __popc(mask);
    __syncthreads();
    int woff = 0;
#pragma unroll
    for (int w = 0; w < 4; w++)
        if (w < wid) woff += s_wcnt[w];
    if (pass) {
        int pos = woff + __popc(mask & ((1u << lane) - 1u));
        s_fast[pos * 3 + 0] = eF0;
        s_fast[pos * 3 + 1] = eF1;
        s_fast[pos * 3 + 2] = eF2;
        s_slow[pos * 3 + 0] = eS0;
        s_slow[pos * 3 + 1] = eS1;
        s_slow[pos * 3 + 2] = eS2;
    }
    if (tid == 0) {
        int tot = 0;
#pragma unroll
        for (int w = 0; w < 4; w++) tot += s_wcnt[w];
        s_n = tot;
    }
    __syncthreads();
    int nf = s_n;

    // ---- per-pixel loop: 2 pixels/thread (rows ty and ty+8) ----
    int xi = gx + threadIdx.x;
    int yiA = gy + threadIdx.y;
    int yiB = yiA + 8;
    float px  = (float)xi + 0.5f;
    float pyA = (float)yiA + 0.5f;
    float pyB = (float)yiB + 0.5f;

    float accA = 0.0f, accB = 0.0f;
    for (int i = 0; i < nf; i++) {
        float4 f0 = s_fast[i * 3 + 0];
        float4 f1 = s_fast[i * 3 + 1];
        float4 f2 = s_fast[i * 3 + 2];

        // pixel A line distances
        float A0 = fmaf(f0.x, px, fmaf(f0.y, pyA, f0.z));
        float A1 = fmaf(f1.x, px, fmaf(f1.y, pyA, f1.z));
        float A2 = fmaf(f2.x, px, fmaf(f2.y, pyA, f2.z));
        // pixel B line distances
        float B0 = fmaf(f0.x, px, fmaf(f0.y, pyB, f0.z));
        float B1 = fmaf(f1.x, px, fmaf(f1.y, pyB, f1.z));
        float B2 = fmaf(f2.x, px, fmaf(f2.y, pyB, f2.z));

        float AmnS = fminf(A0, fminf(A1, A2));
        float BmnS = fminf(B0, fminf(B1, B2));
        bool inA = (AmnS >= 0.0f);
        bool inB = (BmnS >= 0.0f);

        float Aab = fminf(fabsf(A0), fminf(fabsf(A1), fabsf(A2)));
        float Bab = fminf(fabsf(B0), fminf(fabsf(B1), fabsf(B2)));

        bool needA = inA || (Aab <= SQRT_BLUR_SAFE);
        bool needB = inB || (Bab <= SQRT_BLUR_SAFE);

        if (needA || needB) {
            // exact segment-distance path (R4 math, inv packed in f_k.w)
            float4 s0 = s_slow[i * 3 + 0];
            float4 s1 = s_slow[i * 3 + 1];
            float4 s2 = s_slow[i * 3 + 2];

            float apx0 = px - s0.x, apx1 = px - s1.x, apx2 = px - s2.x;

            if (needA) {
                float ap0y = pyA - s0.y;
                float t0 = fminf(fmaxf((apx0 * s0.z + ap0y * s0.w) * f0.w, 0.0f), 1.0f);
                float q0x = apx0 - t0 * s0.z, q0y = ap0y - t0 * s0.w;
                float d0 = q0x * q0x + q0y * q0y;

                float ap1y = pyA - s1.y;
                float t1 = fminf(fmaxf((apx1 * s1.z + ap1y * s1.w) * f1.w, 0.0f), 1.0f);
                float q1x = apx1 - t1 * s1.z, q1y = ap1y - t1 * s1.w;
                float d1 = q1x * q1x + q1y * q1y;

                float ap2y = pyA - s2.y;
                float t2 = fminf(fmaxf((apx2 * s2.z + ap2y * s2.w) * f2.w, 0.0f), 1.0f);
                float q2x = apx2 - t2 * s2.z, q2y = ap2y - t2 * s2.w;
                float d2 = q2x * q2x + q2y * q2y;

                float d2min = fminf(d0, fminf(d1, d2));
                if (inA || (d2min <= BLUR_F)) {
                    float xarg = (inA ? d2min : -d2min) * (1.0f / SIGMA_F);
                    accA -= __logf(1.0f + __expf(xarg));   // softplus
                }
            }
            if (needB) {
                float ap0y = pyB - s0.y;
                float t0 = fminf(fmaxf((apx0 * s0.z + ap0y * s0.w) * f0.w, 0.0f), 1.0f);
                float q0x = apx0 - t0 * s0.z, q0y = ap0y - t0 * s0.w;
                float d0 = q0x * q0x + q0y * q0y;

                float ap1y = pyB - s1.y;
                float t1 = fminf(fmaxf((apx1 * s1.z + ap1y * s1.w) * f1.w, 0.0f), 1.0f);
                float q1x = apx1 - t1 * s1.z, q1y = ap1y - t1 * s1.w;
                float d1 = q1x * q1x + q1y * q1y;

                float ap2y = pyB - s2.y;
                float t2 = fminf(fmaxf((apx2 * s2.z + ap2y * s2.w) * f2.w, 0.0f), 1.0f);
                float q2x = apx2 - t2 * s2.z, q2y = ap2y - t2 * s2.w;
                float d2 = q2x * q2x + q2y * q2y;

                float d2min = fminf(d0, fminf(d1, d2));
                if (inB || (d2min <= BLUR_F)) {
                    float xarg = (inB ? d2min : -d2min) * (1.0f / SIGMA_F);
                    accB -= __logf(1.0f + __expf(xarg));   // softplus
                }
            }
        }

        // Warp early exit every 4 iterations (output-invisible, see R7).
        if ((i & EXIT_CHECK_MASK) == EXIT_CHECK_MASK) {
            bool live = (accA > DONE_THRESH) || (accB > DONE_THRESH);
            if (__ballot_sync(0xffffffffu, live) == 0u) {
                accA = SENTINEL;
                accB = SENTINEL;
                break;
            }
        }
    }
    // lanes that crossed the threshold individually keep exact partials; the
    // uniform sentinel applies only on whole-warp exit (values <= -100 either
    // way -> alpha bits identical).

    // publish this group's partials (release: store -> fence -> ticket RMW)
    {
        int base = (tile * NGROUP + grp) * PIX_PER_CTA;
        __stcg(&g_acc[base + tid], accA);
        __stcg(&g_acc[base + TPB + tid], accB);
    }
    __threadfence();

    // ---- per-tile ticket: last group CTA combines this tile ----
    if (tid == 0) {
        int old = atomicAdd(&g_tile_ticket[tile], 1);
        s_flag = (old == NGROUP - 1) ? 1 : 0;
        __threadfence();   // ACQUIRE side: pairs with writers' release fences
    }
    __syncthreads();
    if (s_flag == 0) return;

    // combine groups for this tile — FIXED order (deterministic)
    float totA = 0.0f, totB = 0.0f;
#pragma unroll
    for (int g = 0; g < NGROUP; g++) {
        int base = (tile * NGROUP + g) * PIX_PER_CTA;
        totA += __ldcg(&g_acc[base + tid]);
        totB += __ldcg(&g_acc[base + TPB + tid]);
    }
    float alphaA = (totA < -87.0f) ? 1.0f : (1.0f - __expf(totA));
    float alphaB = (totB < -87.0f) ? 1.0f : (1.0f - __expf(totB));

    float diff = 0.0f;
    if (xi < W_IMG) {
        int pixA = yiA * W_IMG + xi;
        int pixB = yiB * W_IMG + xi;
        out[1 + pixA] = alphaA;
        out[1 + pixB] = alphaB;
        diff = fabsf(alphaA - gt[pixA]) + fabsf(alphaB - gt[pixB]);
    }

    // block-reduce |diff| (128 threads)
    s_red[tid] = diff;
    __syncthreads();
#pragma unroll
    for (int off = 64; off > 0; off >>= 1) {
        if (tid < off) s_red[tid] += s_red[tid + off];
        __syncthreads();
    }
    if (tid == 0) {
        __stcg(&g_tilepart[tile], s_red[0]);
        __threadfence();   // release for g_tilepart
        int t = atomicAdd(&g_global_ticket, 1);
        s_flag = (t == NTILES - 1) ? 2 : 0;
        __threadfence();   // ACQUIRE side for the final-stage loads
    }
    __syncthreads();
    if (s_flag != 2) return;

    // ---- final: last tile sums 135 tile partials (fixed order) + resets ----
    float v = 0.0f;
    for (int j = tid; j < NTILES; j += TPB)
        v += __ldcg(&g_tilepart[j]);
    s_red[tid] = v;
    __syncthreads();
#pragma unroll
    for (int off = 64; off > 0; off >>= 1) {
        if (tid < off) s_red[tid] += s_red[tid + off];
        __syncthreads();
    }
    if (tid == 0) out[0] = s_red[0] * (1.0f / (float)NPIX);

    // reset tickets for next graph replay
    for (int j = tid; j < NTILES; j += TPB) g_tile_ticket[j] = 0;
    if (tid == 0) g_global_ticket = 0;
}

extern "C" void kernel_launch(void* const* d_in, const int* in_sizes, int n_in,
                              void* d_out, int out_size) {
    const float* verts = (const float*)d_in[0];
    const float* gt    = (const float*)d_in[1];
    const int*   faces = (const int*)d_in[2];
    float* out = (float*)d_out;

    dim3 grid(TILES_X, TILES_Y, NGROUP);
    dim3 block(16, 8);
    fused_sil_kernel<<<grid, block>>>(verts, gt, faces, out);
}